// round 1
// baseline (speedup 1.0000x reference)
#include <cuda_runtime.h>
#include <stdint.h>

// LSTM: H=50 hidden, input dim 1, T=1024 steps, B batch elements (independent).
// One block per batch element. Thread j (0..199) owns gate row j:
//   gate_j = b_ih[j]+b_hh[j] + x_t*W_ih[j] + sum_k W_hh[j][k]*h[k]
// W_hh row held in registers, packed as f32x2 pairs; h broadcast via shared
// memory, loaded as LDS.128 (ulonglong2 -> two f32x2 operands for free).
// Gate order (PyTorch): i[0:50], f[50:100], g[100:150], o[150:200].

#define HH 50
#define GG 200        // 4*H
#define TT 1024
#define BT 224        // block threads (7 warps, 200 active)
#define KP 52         // H padded to multiple of 4

__device__ __forceinline__ float sigf(float x) {
    return 1.0f / (1.0f + __expf(-x));
}
__device__ __forceinline__ float tanhfast(float x) {
    // tanh(x) = 2*sigmoid(2x) - 1  (saturates correctly for large |x|)
    return fmaf(2.0f, sigf(2.0f * x), -1.0f);
}

__device__ __forceinline__ void fma2(unsigned long long& d,
                                     unsigned long long a,
                                     unsigned long long b) {
    asm("fma.rn.f32x2 %0, %1, %2, %0;" : "+l"(d) : "l"(a), "l"(b));
}

__global__ void __launch_bounds__(BT, 4)
lstm_kernel(const float* __restrict__ x,      // [B, T, 1]
            const float* __restrict__ W_ih,   // [200, 1]
            const float* __restrict__ W_hh,   // [200, 50]
            const float* __restrict__ b_ih,   // [200]
            const float* __restrict__ b_hh,   // [200]
            const float* __restrict__ W_lin,  // [1, 50]
            const float* __restrict__ b_lin,  // [1]
            float* __restrict__ out)          // [B, 1]
{
    __shared__ __align__(16) float h_sh[KP];
    __shared__ float act_sh[GG];
    __shared__ float x_sh[TT];

    const int j = threadIdx.x;
    const int b = blockIdx.x;

    // Stage this batch element's x row into shared.
    for (int i = j; i < TT; i += BT) x_sh[i] = x[(size_t)b * TT + i];
    if (j < KP) h_sh[j] = 0.0f;   // h0 = 0, padding lanes stay 0 forever

    float wih = 0.0f, bias = 0.0f;
    unsigned long long wp[KP / 2];
    if (j < GG) {
        wih  = W_ih[j];
        bias = b_ih[j] + b_hh[j];
        #pragma unroll
        for (int q = 0; q < KP / 2; q++) {
            float lo = (2 * q     < HH) ? W_hh[j * HH + 2 * q]     : 0.0f;
            float hi = (2 * q + 1 < HH) ? W_hh[j * HH + 2 * q + 1] : 0.0f;
            wp[q] = ((unsigned long long)__float_as_uint(hi) << 32)
                  |  (unsigned long long)__float_as_uint(lo);
        }
    }
    const bool gate_g = (j >= 100 && j < 150);
    float c = 0.0f;   // cell state, owned by threads 0..49

    __syncthreads();

    for (int t = 0; t < TT; t++) {
        if (j < GG) {
            float base = fmaf(x_sh[t], wih, bias);
            unsigned long long a0 = (unsigned long long)__float_as_uint(base);
            unsigned long long a1 = 0ull;
            const ulonglong2* h2 = (const ulonglong2*)h_sh;
            #pragma unroll
            for (int q = 0; q < 13; q++) {
                ulonglong2 hv = h2[q];          // LDS.128, broadcast
                fma2(a0, wp[2 * q],     hv.x);  // h[4q], h[4q+1]
                fma2(a1, wp[2 * q + 1], hv.y);  // h[4q+2], h[4q+3]
            }
            float s = (__uint_as_float((unsigned)a0) +
                       __uint_as_float((unsigned)(a0 >> 32))) +
                      (__uint_as_float((unsigned)a1) +
                       __uint_as_float((unsigned)(a1 >> 32)));
            act_sh[j] = gate_g ? tanhfast(s) : sigf(s);
        }
        __syncthreads();
        if (j < HH) {
            float gi = act_sh[j];
            float gf = act_sh[j + 50];
            float gg = act_sh[j + 100];
            float go = act_sh[j + 150];
            c = fmaf(gf, c, gi * gg);
            h_sh[j] = go * tanhfast(c);
        }
        __syncthreads();
    }

    // Linear head on last hidden state (tiny; single thread is fine).
    if (j == 0) {
        float s = b_lin[0];
        #pragma unroll 1
        for (int k = 0; k < HH; k++) s = fmaf(h_sh[k], W_lin[k], s);
        out[b] = s;
    }
}

extern "C" void kernel_launch(void* const* d_in, const int* in_sizes, int n_in,
                              void* d_out, int out_size) {
    const float* x     = (const float*)d_in[0];
    const float* W_ih  = (const float*)d_in[1];
    const float* W_hh  = (const float*)d_in[2];
    const float* b_ih  = (const float*)d_in[3];
    const float* b_hh  = (const float*)d_in[4];
    const float* W_lin = (const float*)d_in[5];
    const float* b_lin = (const float*)d_in[6];
    float* out = (float*)d_out;

    int B = in_sizes[0] / TT;   // x has B*T*1 elements
    lstm_kernel<<<B, BT>>>(x, W_ih, W_hh, b_ih, b_hh, W_lin, b_lin, out);
}